// round 2
// baseline (speedup 1.0000x reference)
#include <cuda_runtime.h>
#include <cstddef>

#define H    400
#define CC   4
#define NN   16
#define OO   32
#define RR   4
#define HH   (H*H)          // 160000
#define JQ   (H/4)          // 100 j-quads per row
#define MPITCH 404          // padded smem pitch (floats) in kMarg

// Static device scratch (no runtime allocation allowed)
__device__ float g_T [(size_t)OO*CC*HH];   // 81.92 MB : T[o][c][i][j]
__device__ float g_XT[(size_t)NN*CC*HH];   // 40.96 MB : XT[n][c][j][k] = x[n][c][k][j]
__device__ float g_rows[NN*OO*H];          // rows[n][o][i] (+bias folded)
__device__ float g_cols[NN*OO*H];          // cols[n][o][j]

// ---------------------------------------------------------------------------
// Kernel 1: build T[o,c,i,j] = sum_r L[o,c,i,r] * L[o,c,j,r]
// grid = 128 (one block per (o,c) slice), block = 256
// ---------------------------------------------------------------------------
__global__ __launch_bounds__(256)
void kT(const float* __restrict__ L, float* __restrict__ T)
{
    const int s = blockIdx.x;                 // s = o*CC + c
    const float* Lp = L + (size_t)s * (H*RR);
    float*       Tp = T + (size_t)s * HH;

    __shared__ float sL[H*RR];                // [i][r], 6.4 KB
    for (int idx = threadIdx.x; idx < H*RR; idx += 256) sL[idx] = Lp[idx];
    __syncthreads();

    // items: 100 i-tiles (of 4) x 100 j-quads
    for (int item = threadIdx.x; item < 10000; item += 256) {
        const int it = item / 100;
        const int jq = item % 100;
        const int i0 = it * 4, j0 = jq * 4;

        float4 li[4], lj[4];
        #pragma unroll
        for (int d = 0; d < 4; d++) {
            li[d] = *reinterpret_cast<const float4*>(&sL[(i0 + d) * 4]);
            lj[d] = *reinterpret_cast<const float4*>(&sL[(j0 + d) * 4]);
        }
        #pragma unroll
        for (int d = 0; d < 4; d++) {
            float4 v;
            v.x = li[d].x*lj[0].x + li[d].y*lj[0].y + li[d].z*lj[0].z + li[d].w*lj[0].w;
            v.y = li[d].x*lj[1].x + li[d].y*lj[1].y + li[d].z*lj[1].z + li[d].w*lj[1].w;
            v.z = li[d].x*lj[2].x + li[d].y*lj[2].y + li[d].z*lj[2].z + li[d].w*lj[2].w;
            v.w = li[d].x*lj[3].x + li[d].y*lj[3].y + li[d].z*lj[3].z + li[d].w*lj[3].w;
            *reinterpret_cast<float4*>(&Tp[(size_t)(i0 + d) * H + j0]) = v;
        }
    }
}

// ---------------------------------------------------------------------------
// Kernel 2: transpose each (n,c) slice: XT[n,c,j,k] = x[n,c,k,j]
// grid = (13, 13, 64), block = (32, 8)
// ---------------------------------------------------------------------------
__global__ __launch_bounds__(256)
void kTrans(const float* __restrict__ X, float* __restrict__ XT)
{
    __shared__ float t[32][33];
    const int s = blockIdx.z;
    const float* src = X  + (size_t)s * HH;
    float*       dst = XT + (size_t)s * HH;

    const int j = blockIdx.x * 32 + threadIdx.x;
    #pragma unroll
    for (int m = 0; m < 32; m += 8) {
        const int k = blockIdx.y * 32 + threadIdx.y + m;
        if (k < H && j < H)
            t[threadIdx.y + m][threadIdx.x] = src[(size_t)k * H + j];
    }
    __syncthreads();
    const int k2 = blockIdx.y * 32 + threadIdx.x;
    #pragma unroll
    for (int m = 0; m < 32; m += 8) {
        const int j2 = blockIdx.x * 32 + threadIdx.y + m;
        if (j2 < H && k2 < H)
            dst[(size_t)j2 * H + k2] = t[threadIdx.x][threadIdx.y + m];
    }
}

// ---------------------------------------------------------------------------
// Kernel 3: marginal.  outM[n,o,i] = sum_{c,k} Xp[n,c,i,k] * T[o,c,i,k] (+bias[o])
// grid = (400, 2) : i, o-half (16 o each).  block = 256.
// dyn smem: sX[64][MPITCH] + sT[64][MPITCH]  (rows indexed by n*4+c / o'*4+c)
// ---------------------------------------------------------------------------
__global__ __launch_bounds__(256)
void kMarg(const float* __restrict__ Xp, const float* __restrict__ T,
           float* __restrict__ outM, const float* __restrict__ bias)
{
    extern __shared__ float sm[];
    float* sX = sm;                     // 64 * MPITCH
    float* sT = sm + 64 * MPITCH;       // 64 * MPITCH

    const int i    = blockIdx.x;
    const int half = blockIdx.y;        // o in [half*16, half*16+16)
    const int tid  = threadIdx.x;

    // Load X rows: (n*4+c) -> Xp[((n*4+c)*H + i)*H + k], 64 rows x 100 quads
    for (int idx = tid; idx < 64 * JQ; idx += 256) {
        const int row = idx / JQ, q = idx % JQ;
        float4 v = *reinterpret_cast<const float4*>(
            &Xp[((size_t)row * H + i) * H + 4 * q]);
        *reinterpret_cast<float4*>(&sX[row * MPITCH + 4 * q]) = v;
    }
    // Load T rows: row = o'*4+c, o = half*16 + o'
    for (int idx = tid; idx < 64 * JQ; idx += 256) {
        const int row = idx / JQ, q = idx % JQ;
        const int op = row >> 2, c = row & 3;
        const int o  = half * 16 + op;
        float4 v = *reinterpret_cast<const float4*>(
            &T[(((size_t)o * CC + c) * H + i) * H + 4 * q]);
        *reinterpret_cast<float4*>(&sT[row * MPITCH + 4 * q]) = v;
    }
    __syncthreads();

    // Compute: 16 pair-tiles (4n x 4o') x 16 k-slices
    const int tt = tid & 15, ks = tid >> 4;
    const int nt = (tt & 3) * 4;       // n base
    const int ot = (tt >> 2) * 4;      // o' base

    float acc[4][4];
    #pragma unroll
    for (int a = 0; a < 4; a++)
        #pragma unroll
        for (int b = 0; b < 4; b++) acc[a][b] = 0.f;

    for (int q = ks; q < JQ; q += 16) {
        #pragma unroll
        for (int c = 0; c < 4; c++) {
            float4 xv[4], tv[4];
            #pragma unroll
            for (int a = 0; a < 4; a++)
                xv[a] = *reinterpret_cast<const float4*>(
                    &sX[((nt + a) * 4 + c) * MPITCH + 4 * q]);
            #pragma unroll
            for (int b = 0; b < 4; b++)
                tv[b] = *reinterpret_cast<const float4*>(
                    &sT[((ot + b) * 4 + c) * MPITCH + 4 * q]);
            #pragma unroll
            for (int a = 0; a < 4; a++)
                #pragma unroll
                for (int b = 0; b < 4; b++)
                    acc[a][b] += xv[a].x * tv[b].x + xv[a].y * tv[b].y
                               + xv[a].z * tv[b].z + xv[a].w * tv[b].w;
        }
    }
    __syncthreads();

    // Reduce over 16 k-slices via smem (reuse sX region)
    float* red = sX;   // needs 16*16*16 = 4096 floats
    #pragma unroll
    for (int a = 0; a < 4; a++)
        #pragma unroll
        for (int b = 0; b < 4; b++)
            red[(tt * 16 + a * 4 + b) * 16 + ks] = acc[a][b];
    __syncthreads();

    {
        float v = 0.f;
        #pragma unroll
        for (int s2 = 0; s2 < 16; s2++) v += red[tid * 16 + s2];
        const int tt2 = tid >> 4, ab = tid & 15;
        const int a = ab >> 2, b = ab & 3;
        const int n  = (tt2 & 3) * 4 + a;
        const int op = (tt2 >> 2) * 4 + b;
        const int o  = half * 16 + op;
        if (bias) v += bias[o];
        outM[((size_t)n * OO + o) * H + i] = v;
    }
}

// ---------------------------------------------------------------------------
// Kernel 4: output.
// out[n,o,i,j] = rows[n,o,i](+bias) + cols[n,o,j] - sum_c X[n,c,i,j]*T[o,c,i,j]
// grid = (400, 4) : i, o-group of 8.  block = 256.
// dyn smem: sT[32][400] + sX[64][400] + sr[128]
// ---------------------------------------------------------------------------
__global__ __launch_bounds__(256)
void kOut(const float* __restrict__ X, const float* __restrict__ T,
          const float* __restrict__ rows, const float* __restrict__ cols,
          float* __restrict__ out)
{
    extern __shared__ float sm[];
    float* sT = sm;                    // 32 * 400
    float* sX = sm + 32 * H;           // 64 * 400
    float* sr = sX + 64 * H;           // 128

    const int i  = blockIdx.x;
    const int og = blockIdx.y;         // 0..3
    const int o0 = og * 8;
    const int tid = threadIdx.x;

    // stage T rows: row = o'*4+c (32 rows)
    for (int idx = tid; idx < 32 * JQ; idx += 256) {
        const int row = idx / JQ, q = idx % JQ;
        const int op = row >> 2, c = row & 3;
        float4 v = *reinterpret_cast<const float4*>(
            &T[(((size_t)(o0 + op) * CC + c) * H + i) * H + 4 * q]);
        *reinterpret_cast<float4*>(&sT[row * H + 4 * q]) = v;
    }
    // stage X rows: row = n*4+c (64 rows)
    for (int idx = tid; idx < 64 * JQ; idx += 256) {
        const int row = idx / JQ, q = idx % JQ;
        float4 v = *reinterpret_cast<const float4*>(
            &X[((size_t)row * H + i) * H + 4 * q]);
        *reinterpret_cast<float4*>(&sX[row * H + 4 * q]) = v;
    }
    // stage rows scalars: pair = n*8 + o'
    if (tid < 128) {
        const int n = tid >> 3, op = tid & 7;
        sr[tid] = rows[((size_t)n * OO + (o0 + op)) * H + i];
    }
    __syncthreads();

    // 128 (n,o') pairs x 100 j-quads = 12800 items
    for (int it = tid; it < 128 * JQ; it += 256) {
        const int jq  = it % JQ;
        const int pair = it / JQ;
        const int n = pair >> 3, op = pair & 7;
        const int o = o0 + op;

        float4 cv = *reinterpret_cast<const float4*>(
            &cols[((size_t)n * OO + o) * H + 4 * jq]);
        const float base = sr[pair];
        float4 acc;
        acc.x = base + cv.x; acc.y = base + cv.y;
        acc.z = base + cv.z; acc.w = base + cv.w;

        #pragma unroll
        for (int c = 0; c < 4; c++) {
            float4 xv = *reinterpret_cast<const float4*>(&sX[(n * 4 + c) * H + 4 * jq]);
            float4 tv = *reinterpret_cast<const float4*>(&sT[(op * 4 + c) * H + 4 * jq]);
            acc.x -= xv.x * tv.x;
            acc.y -= xv.y * tv.y;
            acc.z -= xv.z * tv.z;
            acc.w -= xv.w * tv.w;
        }
        *reinterpret_cast<float4*>(
            &out[(((size_t)n * OO + o) * H + i) * H + 4 * jq]) = acc;
    }
}

// ---------------------------------------------------------------------------
extern "C" void kernel_launch(void* const* d_in, const int* in_sizes, int n_in,
                              void* d_out, int out_size)
{
    const float* x    = (const float*)d_in[0];
    const float* wL   = (const float*)d_in[1];
    const float* bias = (const float*)d_in[2];
    float*       out  = (float*)d_out;

    float *Tbuf, *XTbuf, *rowsBuf, *colsBuf;
    cudaGetSymbolAddress((void**)&Tbuf,    g_T);
    cudaGetSymbolAddress((void**)&XTbuf,   g_XT);
    cudaGetSymbolAddress((void**)&rowsBuf, g_rows);
    cudaGetSymbolAddress((void**)&colsBuf, g_cols);

    const int smMarg = 2 * 64 * MPITCH * sizeof(float);           // 206848
    const int smOut  = (32 * H + 64 * H + 128) * sizeof(float);   // 154112
    cudaFuncSetAttribute(kMarg, cudaFuncAttributeMaxDynamicSharedMemorySize, smMarg);
    cudaFuncSetAttribute(kOut,  cudaFuncAttributeMaxDynamicSharedMemorySize, smOut);

    // 1. build T ; 2. transpose x  (independent, same stream => ordered, fine)
    kT<<<OO * CC, 256>>>(wL, Tbuf);
    kTrans<<<dim3(13, 13, NN * CC), dim3(32, 8)>>>(x, XTbuf);

    // 3. marginals (rows gets bias folded in; cols does not)
    kMarg<<<dim3(H, 2), 256, smMarg>>>(x,     Tbuf, rowsBuf, bias);
    kMarg<<<dim3(H, 2), 256, smMarg>>>(XTbuf, Tbuf, colsBuf, nullptr);

    // 4. fused output
    kOut<<<dim3(H, 4), 256, smOut>>>(x, Tbuf, rowsBuf, colsBuf, out);
}

// round 3
// speedup vs baseline: 1.2681x; 1.2681x over previous
#include <cuda_runtime.h>
#include <cstddef>

#define H    400
#define CC   4
#define NN   16
#define OO   32
#define RR   4
#define HH   (H*H)          // 160000
#define JQ   (H/4)          // 100 quads per row

// Static device scratch (no runtime allocation allowed)
__device__ float g_T [(size_t)OO*CC*HH];   // 81.92 MB : T[o][c][i][j]
__device__ float g_XT[(size_t)NN*CC*HH];   // 40.96 MB : XT[n][c][j][k] = x[n][c][k][j]
__device__ float g_rows[NN*OO*H];          // rows[n][o][i] (+bias folded)
__device__ float g_cols[NN*OO*H];          // cols[n][o][j]

// ---------------------------------------------------------------------------
// Kernel 1: build T[o,c,i,j] = sum_r L[o,c,i,r] * L[o,c,j,r]
// grid = (128, 2), block = 256
// ---------------------------------------------------------------------------
__global__ __launch_bounds__(256)
void kT(const float* __restrict__ L, float* __restrict__ T)
{
    const int s = blockIdx.x;                 // s = o*CC + c
    const float* Lp = L + (size_t)s * (H*RR);
    float*       Tp = T + (size_t)s * HH;

    __shared__ float sL[H*RR];                // [i][r], 6.4 KB
    for (int idx = threadIdx.x; idx < H*RR; idx += 256) sL[idx] = Lp[idx];
    __syncthreads();

    // 10000 items = 100 i-tiles x 100 j-quads, split in halves across blockIdx.y
    const int base = blockIdx.y * 5000;
    for (int loc = threadIdx.x; loc < 5000; loc += 256) {
        const int item = base + loc;
        const int it = item / 100;
        const int jq = item % 100;
        const int i0 = it * 4, j0 = jq * 4;

        float4 li[4], lj[4];
        #pragma unroll
        for (int d = 0; d < 4; d++) {
            li[d] = *reinterpret_cast<const float4*>(&sL[(i0 + d) * 4]);
            lj[d] = *reinterpret_cast<const float4*>(&sL[(j0 + d) * 4]);
        }
        #pragma unroll
        for (int d = 0; d < 4; d++) {
            float4 v;
            v.x = li[d].x*lj[0].x + li[d].y*lj[0].y + li[d].z*lj[0].z + li[d].w*lj[0].w;
            v.y = li[d].x*lj[1].x + li[d].y*lj[1].y + li[d].z*lj[1].z + li[d].w*lj[1].w;
            v.z = li[d].x*lj[2].x + li[d].y*lj[2].y + li[d].z*lj[2].z + li[d].w*lj[2].w;
            v.w = li[d].x*lj[3].x + li[d].y*lj[3].y + li[d].z*lj[3].z + li[d].w*lj[3].w;
            *reinterpret_cast<float4*>(&Tp[(size_t)(i0 + d) * H + j0]) = v;
        }
    }
}

// ---------------------------------------------------------------------------
// Kernel 2: transpose each (n,c) slice: XT[n,c,j,k] = x[n,c,k,j]
// ---------------------------------------------------------------------------
__global__ __launch_bounds__(256)
void kTrans(const float* __restrict__ X, float* __restrict__ XT)
{
    __shared__ float t[32][33];
    const int s = blockIdx.z;
    const float* src = X  + (size_t)s * HH;
    float*       dst = XT + (size_t)s * HH;

    const int j = blockIdx.x * 32 + threadIdx.x;
    #pragma unroll
    for (int m = 0; m < 32; m += 8) {
        const int k = blockIdx.y * 32 + threadIdx.y + m;
        if (k < H && j < H)
            t[threadIdx.y + m][threadIdx.x] = src[(size_t)k * H + j];
    }
    __syncthreads();
    const int k2 = blockIdx.y * 32 + threadIdx.x;
    #pragma unroll
    for (int m = 0; m < 32; m += 8) {
        const int j2 = blockIdx.x * 32 + threadIdx.y + m;
        if (j2 < H && k2 < H)
            dst[(size_t)j2 * H + k2] = t[threadIdx.x][threadIdx.y + m];
    }
}

// ---------------------------------------------------------------------------
// Kernel 3: marginal.  outM[n,o,i] = sum_{c,k} Xp[n,c,i,k] * T[o,c,i,k] (+bias)
// grid = (400, 2) : i, o-half.  block = 256.
// k-chunked smem: sX[64][32] float4 + sT[64][32] float4 = 64 KB -> 3 blocks/SM
// ---------------------------------------------------------------------------
__global__ __launch_bounds__(256)
void kMarg(const float* __restrict__ Xp, const float* __restrict__ T,
           float* __restrict__ outM, const float* __restrict__ bias)
{
    extern __shared__ float sm[];
    float4* sX = reinterpret_cast<float4*>(sm);   // 64*32
    float4* sT = sX + 64 * 32;                    // 64*32

    const int i    = blockIdx.x;
    const int half = blockIdx.y;
    const int tid  = threadIdx.x;
    const int ks = tid & 15;       // k-slice lane (consecutive quads per warp)
    const int tt = tid >> 4;       // tile id 0..15
    const int nt = (tt & 3) * 4;
    const int ot = (tt >> 2) * 4;

    float acc[4][4] = {};

    #pragma unroll
    for (int ch = 0; ch < 4; ch++) {
        const int q0 = ch * 32;
        const int cq = (ch < 3) ? 32 : 4;     // quads in this chunk
        __syncthreads();
        // load X: rows r = c*16+n
        for (int idx = tid; idx < 64 * cq; idx += 256) {
            int r, q2;
            if (ch < 3) { r = idx >> 5; q2 = idx & 31; } else { r = idx >> 2; q2 = idx & 3; }
            const int c = r >> 4, n = r & 15;
            sX[r * 32 + q2] = *reinterpret_cast<const float4*>(
                &Xp[(((size_t)(n * 4 + c)) * H + i) * H + (q0 + q2) * 4]);
        }
        // load T: rows r = c*16+o'
        for (int idx = tid; idx < 64 * cq; idx += 256) {
            int r, q2;
            if (ch < 3) { r = idx >> 5; q2 = idx & 31; } else { r = idx >> 2; q2 = idx & 3; }
            const int c = r >> 4, op = r & 15;
            const int o = half * 16 + op;
            sT[r * 32 + q2] = *reinterpret_cast<const float4*>(
                &T[((((size_t)o) * CC + c) * H + i) * H + (q0 + q2) * 4]);
        }
        __syncthreads();
        for (int q = ks; q < cq; q += 16) {
            #pragma unroll
            for (int c = 0; c < 4; c++) {
                float4 xv[4], tv[4];
                #pragma unroll
                for (int a = 0; a < 4; a++) xv[a] = sX[(c * 16 + nt + a) * 32 + q];
                #pragma unroll
                for (int b = 0; b < 4; b++) tv[b] = sT[(c * 16 + ot + b) * 32 + q];
                #pragma unroll
                for (int a = 0; a < 4; a++)
                    #pragma unroll
                    for (int b = 0; b < 4; b++)
                        acc[a][b] += xv[a].x * tv[b].x + xv[a].y * tv[b].y
                                   + xv[a].z * tv[b].z + xv[a].w * tv[b].w;
            }
        }
    }
    __syncthreads();

    // reduce the 16 k-slices through smem
    float* red = sm;   // 4096 floats, fits in sX region
    #pragma unroll
    for (int a = 0; a < 4; a++)
        #pragma unroll
        for (int b = 0; b < 4; b++)
            red[(tt * 16 + a * 4 + b) * 16 + ks] = acc[a][b];
    __syncthreads();

    float v = 0.f;
    #pragma unroll
    for (int s2 = 0; s2 < 16; s2++) v += red[tid * 16 + s2];
    const int tt2 = tid >> 4, ab = tid & 15;
    const int a = ab >> 2, b = ab & 3;
    const int n  = (tt2 & 3) * 4 + a;
    const int op = (tt2 >> 2) * 4 + b;
    const int o  = half * 16 + op;
    if (bias) v += bias[o];
    outM[((size_t)n * OO + o) * H + i] = v;
}

// ---------------------------------------------------------------------------
// Kernel 4: out[n,o,i,j] = rows[n,o,i] + cols[n,o,j] - sum_c X[n,c,i,j]*T[o,c,i,j]
// grid = (400, 4) : i, o-group of 8.  block = 256.
// j-chunked smem: sX[64][32]f4 + sT[32][32]f4 + sr[128] = 49.7 KB -> 4 blocks/SM
// Each thread: 2 n's in registers x all 8 o' -> 2.5x LDS per output byte.
// ---------------------------------------------------------------------------
__global__ __launch_bounds__(256)
void kOut(const float* __restrict__ X, const float* __restrict__ T,
          const float* __restrict__ rows, const float* __restrict__ cols,
          float* __restrict__ out)
{
    extern __shared__ float sm[];
    float4* sX = reinterpret_cast<float4*>(sm);    // 64*32
    float4* sT = sX + 64 * 32;                     // 32*32
    float*  sr = reinterpret_cast<float*>(sT + 32 * 32);  // 128

    const int i   = blockIdx.x;
    const int o0  = blockIdx.y * 8;
    const int tid = threadIdx.x;

    if (tid < 128) {
        const int n = tid >> 3, op = tid & 7;
        sr[tid] = rows[((size_t)n * OO + o0 + op) * H + i];
    }

    const int np = tid >> 5;      // n-pair 0..7 (fixed within warp)
    const int q  = tid & 31;      // quad lane
    const int n0 = np * 2;

    #pragma unroll
    for (int ch = 0; ch < 4; ch++) {
        const int q0 = ch * 32;
        const int cq = (ch < 3) ? 32 : 4;
        __syncthreads();
        for (int idx = tid; idx < 64 * cq; idx += 256) {
            int r, q2;
            if (ch < 3) { r = idx >> 5; q2 = idx & 31; } else { r = idx >> 2; q2 = idx & 3; }
            const int c = r >> 4, n = r & 15;
            sX[r * 32 + q2] = *reinterpret_cast<const float4*>(
                &X[(((size_t)(n * 4 + c)) * H + i) * H + (q0 + q2) * 4]);
        }
        for (int idx = tid; idx < 32 * cq; idx += 256) {
            int r, q2;
            if (ch < 3) { r = idx >> 5; q2 = idx & 31; } else { r = idx >> 2; q2 = idx & 3; }
            const int c = r >> 3, op = r & 7;
            sT[r * 32 + q2] = *reinterpret_cast<const float4*>(
                &T[((((size_t)(o0 + op)) * CC + c) * H + i) * H + (q0 + q2) * 4]);
        }
        __syncthreads();

        if (q < cq) {
            float4 xv[2][4];
            #pragma unroll
            for (int d = 0; d < 2; d++)
                #pragma unroll
                for (int c = 0; c < 4; c++)
                    xv[d][c] = sX[(c * 16 + n0 + d) * 32 + q];

            #pragma unroll
            for (int op = 0; op < 8; op++) {
                float4 tv[4];
                #pragma unroll
                for (int c = 0; c < 4; c++) tv[c] = sT[(c * 8 + op) * 32 + q];
                #pragma unroll
                for (int d = 0; d < 2; d++) {
                    const int n = n0 + d;
                    const int o = o0 + op;
                    float4 cv = *reinterpret_cast<const float4*>(
                        &cols[((size_t)n * OO + o) * H + (q0 + q) * 4]);
                    const float base = sr[n * 8 + op];
                    float4 av;
                    av.x = base + cv.x; av.y = base + cv.y;
                    av.z = base + cv.z; av.w = base + cv.w;
                    #pragma unroll
                    for (int c = 0; c < 4; c++) {
                        av.x -= xv[d][c].x * tv[c].x;
                        av.y -= xv[d][c].y * tv[c].y;
                        av.z -= xv[d][c].z * tv[c].z;
                        av.w -= xv[d][c].w * tv[c].w;
                    }
                    *reinterpret_cast<float4*>(
                        &out[(((size_t)n * OO + o) * H + i) * H + (q0 + q) * 4]) = av;
                }
            }
        }
    }
}

// ---------------------------------------------------------------------------
extern "C" void kernel_launch(void* const* d_in, const int* in_sizes, int n_in,
                              void* d_out, int out_size)
{
    const float* x    = (const float*)d_in[0];
    const float* wL   = (const float*)d_in[1];
    const float* bias = (const float*)d_in[2];
    float*       out  = (float*)d_out;

    float *Tbuf, *XTbuf, *rowsBuf, *colsBuf;
    cudaGetSymbolAddress((void**)&Tbuf,    g_T);
    cudaGetSymbolAddress((void**)&XTbuf,   g_XT);
    cudaGetSymbolAddress((void**)&rowsBuf, g_rows);
    cudaGetSymbolAddress((void**)&colsBuf, g_cols);

    const int smMarg = 2 * 64 * 32 * sizeof(float4);                       // 65536
    const int smOut  = (64 * 32 + 32 * 32) * sizeof(float4) + 128 * 4;     // 49664
    cudaFuncSetAttribute(kMarg, cudaFuncAttributeMaxDynamicSharedMemorySize, smMarg);
    cudaFuncSetAttribute(kOut,  cudaFuncAttributeMaxDynamicSharedMemorySize, smOut);

    kT<<<dim3(OO * CC, 2), 256>>>(wL, Tbuf);
    kTrans<<<dim3(13, 13, NN * CC), dim3(32, 8)>>>(x, XTbuf);

    kMarg<<<dim3(H, 2), 256, smMarg>>>(x,     Tbuf, rowsBuf, bias);
    kMarg<<<dim3(H, 2), 256, smMarg>>>(XTbuf, Tbuf, colsBuf, nullptr);

    kOut<<<dim3(H, 4), 256, smOut>>>(x, Tbuf, rowsBuf, colsBuf, out);
}

// round 4
// speedup vs baseline: 2.6378x; 2.0801x over previous
#include <cuda_runtime.h>
#include <cstddef>
#include <cstdint>

#define H    400
#define CC   4
#define NN   16
#define OO   32
#define RR   4
#define HH   (H*H)          // 160000

// Static device scratch
__device__ float g_T [(size_t)OO*CC*HH];   // 81.92 MB : T[o][c][i][j]
__device__ float g_XT[(size_t)NN*CC*HH];   // 40.96 MB : XT[n][c][j][k]
__device__ float g_rows[NN*OO*H];
__device__ float g_cols[NN*OO*H];

// ---- cp.async helpers ------------------------------------------------------
__device__ __forceinline__ void cp16(void* smem_dst, const void* gmem_src) {
    uint32_t d = (uint32_t)__cvta_generic_to_shared(smem_dst);
    asm volatile("cp.async.cg.shared.global [%0], [%1], 16;\n" :: "r"(d), "l"(gmem_src));
}
__device__ __forceinline__ void cp_commit() {
    asm volatile("cp.async.commit_group;\n");
}
template<int N>
__device__ __forceinline__ void cp_wait() {
    asm volatile("cp.async.wait_group %0;\n" :: "n"(N));
}

// ---------------------------------------------------------------------------
// Kernel 1: T[o,c,i,j] = sum_r L[o,c,i,r]*L[o,c,j,r].  grid=(128,16), block=256
// ---------------------------------------------------------------------------
__global__ __launch_bounds__(256)
void kT(const float* __restrict__ L, float* __restrict__ T)
{
    const int s = blockIdx.x;                 // o*CC + c
    const float* Lp = L + (size_t)s * (H*RR);
    float*       Tp = T + (size_t)s * HH;

    __shared__ float sL[H*RR];
    for (int idx = threadIdx.x; idx < H*RR; idx += 256) sL[idx] = Lp[idx];
    __syncthreads();

    // 10000 items = 100 i-tiles x 100 j-quads, 625 per blockIdx.y
    const int base = blockIdx.y * 625;
    for (int loc = threadIdx.x; loc < 625; loc += 256) {
        const int item = base + loc;
        const int it = item / 100;
        const int jq = item % 100;
        const int i0 = it * 4, j0 = jq * 4;

        float4 li[4], lj[4];
        #pragma unroll
        for (int d = 0; d < 4; d++) {
            li[d] = *reinterpret_cast<const float4*>(&sL[(i0 + d) * 4]);
            lj[d] = *reinterpret_cast<const float4*>(&sL[(j0 + d) * 4]);
        }
        #pragma unroll
        for (int d = 0; d < 4; d++) {
            float4 v;
            v.x = li[d].x*lj[0].x + li[d].y*lj[0].y + li[d].z*lj[0].z + li[d].w*lj[0].w;
            v.y = li[d].x*lj[1].x + li[d].y*lj[1].y + li[d].z*lj[1].z + li[d].w*lj[1].w;
            v.z = li[d].x*lj[2].x + li[d].y*lj[2].y + li[d].z*lj[2].z + li[d].w*lj[2].w;
            v.w = li[d].x*lj[3].x + li[d].y*lj[3].y + li[d].z*lj[3].z + li[d].w*lj[3].w;
            *reinterpret_cast<float4*>(&Tp[(size_t)(i0 + d) * H + j0]) = v;
        }
    }
}

// ---------------------------------------------------------------------------
// Kernel 2: per-(n,c) transpose XT[j,k] = x[k,j]
// ---------------------------------------------------------------------------
__global__ __launch_bounds__(256)
void kTrans(const float* __restrict__ X, float* __restrict__ XT)
{
    __shared__ float t[32][33];
    const int s = blockIdx.z;
    const float* src = X  + (size_t)s * HH;
    float*       dst = XT + (size_t)s * HH;

    const int j = blockIdx.x * 32 + threadIdx.x;
    #pragma unroll
    for (int m = 0; m < 32; m += 8) {
        const int k = blockIdx.y * 32 + threadIdx.y + m;
        if (k < H && j < H)
            t[threadIdx.y + m][threadIdx.x] = src[(size_t)k * H + j];
    }
    __syncthreads();
    const int k2 = blockIdx.y * 32 + threadIdx.x;
    #pragma unroll
    for (int m = 0; m < 32; m += 8) {
        const int j2 = blockIdx.x * 32 + threadIdx.y + m;
        if (j2 < H && k2 < H)
            dst[(size_t)j2 * H + k2] = t[threadIdx.x][threadIdx.y + m];
    }
}

// ---------------------------------------------------------------------------
// Kernel 3: marginal, cp.async double-buffered.
// outM[n,o,i] = sum_{c,k} Xp[n,c,i,k]*T[o,c,i,k] (+bias)
// grid=(400,2), block=256.  7 chunks of 16(+4 tail) quads.
// stage = sX[64][16]f4 + sT[64][16]f4 = 32 KB, x2 stages = 64 KB
// ---------------------------------------------------------------------------
__global__ __launch_bounds__(256, 3)
void kMarg(const float* __restrict__ Xp, const float* __restrict__ T,
           float* __restrict__ outM, const float* __restrict__ bias)
{
    extern __shared__ float sm[];
    float4* s4 = reinterpret_cast<float4*>(sm);   // [2][2048] f4

    const int i    = blockIdx.x;
    const int half = blockIdx.y;
    const int tid  = threadIdx.x;
    const int ks = tid & 15;
    const int tt = tid >> 4;
    const int nt = (tt & 3) * 4;
    const int ot = (tt >> 2) * 4;

    const float* Tb = T + ((size_t)half * 16 * CC * H + i) * H;  // o' stride CC*HH

    auto issue = [&](int ch) {
        const int q0 = ch * 16;
        const int full = (ch < 6);
        const int cq = full ? 16 : 4;
        float4* dX = s4 + (ch & 1) * 2048;
        float4* dT = dX + 1024;
        for (int idx = tid; idx < 64 * cq; idx += 256) {
            const int r  = full ? (idx >> 4) : (idx >> 2);
            const int q2 = full ? (idx & 15) : (idx & 3);
            const int c = r >> 4, n = r & 15;
            cp16(&dX[r * 16 + q2],
                 &Xp[(((size_t)(n * 4 + c)) * H + i) * H + (q0 + q2) * 4]);
        }
        for (int idx = tid; idx < 64 * cq; idx += 256) {
            const int r  = full ? (idx >> 4) : (idx >> 2);
            const int q2 = full ? (idx & 15) : (idx & 3);
            const int c = r >> 4, op = r & 15;
            cp16(&dT[r * 16 + q2],
                 &T[((((size_t)(half * 16 + op)) * CC + c) * H + i) * H + (q0 + q2) * 4]);
        }
        cp_commit();
    };

    float acc[4][4] = {};

    issue(0);
    #pragma unroll 1
    for (int ch = 0; ch < 7; ch++) {
        if (ch + 1 < 7) { issue(ch + 1); cp_wait<1>(); }
        else            { cp_wait<0>(); }
        __syncthreads();

        const int cq = (ch < 6) ? 16 : 4;
        const float4* bX = s4 + (ch & 1) * 2048;
        const float4* bT = bX + 1024;
        if (ks < cq) {
            #pragma unroll
            for (int c = 0; c < 4; c++) {
                float4 xv[4], tv[4];
                #pragma unroll
                for (int a = 0; a < 4; a++) xv[a] = bX[(c * 16 + nt + a) * 16 + ks];
                #pragma unroll
                for (int b = 0; b < 4; b++) tv[b] = bT[(c * 16 + ot + b) * 16 + ks];
                #pragma unroll
                for (int a = 0; a < 4; a++)
                    #pragma unroll
                    for (int b = 0; b < 4; b++)
                        acc[a][b] += xv[a].x * tv[b].x + xv[a].y * tv[b].y
                                   + xv[a].z * tv[b].z + xv[a].w * tv[b].w;
            }
        }
        __syncthreads();
    }

    // reduce 16 k-slices through smem
    float* red = sm;      // 4096 floats
    #pragma unroll
    for (int a = 0; a < 4; a++)
        #pragma unroll
        for (int b = 0; b < 4; b++)
            red[(tt * 16 + a * 4 + b) * 16 + ks] = acc[a][b];
    __syncthreads();

    float v = 0.f;
    #pragma unroll
    for (int s2 = 0; s2 < 16; s2++) v += red[tid * 16 + s2];
    const int tt2 = tid >> 4, ab = tid & 15;
    const int a = ab >> 2, b = ab & 3;
    const int n  = (tt2 & 3) * 4 + a;
    const int op = (tt2 >> 2) * 4 + b;
    const int o  = half * 16 + op;
    if (bias) v += bias[o];
    outM[((size_t)n * OO + o) * H + i] = v;
    (void)Tb;
}

// ---------------------------------------------------------------------------
// Kernel 4: out[n,o,i,j] = rows[n,o,i] + cols[n,o,j] - sum_c X*T
// grid=(400,4), block=256.  4 chunks of 32(+4 tail) quads, cp.async 2-stage.
// stage = sX[64][32]f4 (32KB) + sT[32][32]f4 (16KB) = 48 KB, x2 = 96 KB
// ---------------------------------------------------------------------------
__global__ __launch_bounds__(256, 2)
void kOut(const float* __restrict__ X, const float* __restrict__ T,
          const float* __restrict__ rows, const float* __restrict__ cols,
          float* __restrict__ out)
{
    extern __shared__ float sm[];
    float4* s4 = reinterpret_cast<float4*>(sm);        // [2][3072] f4
    float*  sr = sm + 2 * 3072 * 4;                    // 128 floats

    const int i   = blockIdx.x;
    const int o0  = blockIdx.y * 8;
    const int tid = threadIdx.x;

    if (tid < 128) {
        const int n = tid >> 3, op = tid & 7;
        sr[tid] = rows[((size_t)n * OO + o0 + op) * H + i];
    }

    auto issue = [&](int ch) {
        const int q0 = ch * 32;
        const int full = (ch < 3);
        const int cq = full ? 32 : 4;
        float4* dX = s4 + (ch & 1) * 3072;
        float4* dT = dX + 2048;
        for (int idx = tid; idx < 64 * cq; idx += 256) {
            const int r  = full ? (idx >> 5) : (idx >> 2);
            const int q2 = full ? (idx & 31) : (idx & 3);
            const int c = r >> 4, n = r & 15;
            cp16(&dX[r * 32 + q2],
                 &X[(((size_t)(n * 4 + c)) * H + i) * H + (q0 + q2) * 4]);
        }
        for (int idx = tid; idx < 32 * cq; idx += 256) {
            const int r  = full ? (idx >> 5) : (idx >> 2);
            const int q2 = full ? (idx & 31) : (idx & 3);
            const int c = r >> 3, op = r & 7;
            cp16(&dT[r * 32 + q2],
                 &T[((((size_t)(o0 + op)) * CC + c) * H + i) * H + (q0 + q2) * 4]);
        }
        cp_commit();
    };

    const int np = tid >> 5;       // 0..7
    const int q  = tid & 31;
    const int n0 = np * 2;

    issue(0);
    #pragma unroll 1
    for (int ch = 0; ch < 4; ch++) {
        if (ch + 1 < 4) { issue(ch + 1); cp_wait<1>(); }
        else            { cp_wait<0>(); }
        __syncthreads();

        const int q0 = ch * 32;
        const int cq = (ch < 3) ? 32 : 4;
        const float4* bX = s4 + (ch & 1) * 3072;
        const float4* bT = bX + 2048;

        if (q < cq) {
            float4 xv[2][4];
            #pragma unroll
            for (int d = 0; d < 2; d++)
                #pragma unroll
                for (int c = 0; c < 4; c++)
                    xv[d][c] = bX[(c * 16 + n0 + d) * 32 + q];

            #pragma unroll
            for (int g = 0; g < 2; g++) {           // op groups of 4
                float4 cv[4][2];
                #pragma unroll
                for (int o4 = 0; o4 < 4; o4++)
                    #pragma unroll
                    for (int d = 0; d < 2; d++)
                        cv[o4][d] = __ldg(reinterpret_cast<const float4*>(
                            &cols[((size_t)(n0 + d) * OO + o0 + g * 4 + o4) * H + (q0 + q) * 4]));

                #pragma unroll
                for (int o4 = 0; o4 < 4; o4++) {
                    const int op = g * 4 + o4;
                    float4 tv[4];
                    #pragma unroll
                    for (int c = 0; c < 4; c++) tv[c] = bT[(c * 8 + op) * 32 + q];
                    #pragma unroll
                    for (int d = 0; d < 2; d++) {
                        const int n = n0 + d;
                        const float base = sr[n * 8 + op];
                        float4 av;
                        av.x = base + cv[o4][d].x;
                        av.y = base + cv[o4][d].y;
                        av.z = base + cv[o4][d].z;
                        av.w = base + cv[o4][d].w;
                        #pragma unroll
                        for (int c = 0; c < 4; c++) {
                            av.x -= xv[d][c].x * tv[c].x;
                            av.y -= xv[d][c].y * tv[c].y;
                            av.z -= xv[d][c].z * tv[c].z;
                            av.w -= xv[d][c].w * tv[c].w;
                        }
                        *reinterpret_cast<float4*>(
                            &out[(((size_t)n * OO + o0 + op) * H + i) * H + (q0 + q) * 4]) = av;
                    }
                }
            }
        }
        __syncthreads();
    }
}

// ---------------------------------------------------------------------------
extern "C" void kernel_launch(void* const* d_in, const int* in_sizes, int n_in,
                              void* d_out, int out_size)
{
    const float* x    = (const float*)d_in[0];
    const float* wL   = (const float*)d_in[1];
    const float* bias = (const float*)d_in[2];
    float*       out  = (float*)d_out;

    float *Tbuf, *XTbuf, *rowsBuf, *colsBuf;
    cudaGetSymbolAddress((void**)&Tbuf,    g_T);
    cudaGetSymbolAddress((void**)&XTbuf,   g_XT);
    cudaGetSymbolAddress((void**)&rowsBuf, g_rows);
    cudaGetSymbolAddress((void**)&colsBuf, g_cols);

    const int smMarg = 2 * 2048 * sizeof(float4);              // 65536
    const int smOut  = 2 * 3072 * sizeof(float4) + 128 * 4;    // 98816
    cudaFuncSetAttribute(kMarg, cudaFuncAttributeMaxDynamicSharedMemorySize, smMarg);
    cudaFuncSetAttribute(kOut,  cudaFuncAttributeMaxDynamicSharedMemorySize, smOut);

    kT<<<dim3(OO * CC, 16), 256>>>(wL, Tbuf);
    kTrans<<<dim3(13, 13, NN * CC), dim3(32, 8)>>>(x, XTbuf);

    kMarg<<<dim3(H, 2), 256, smMarg>>>(x,     Tbuf, rowsBuf, bias);
    kMarg<<<dim3(H, 2), 256, smMarg>>>(XTbuf, Tbuf, colsBuf, nullptr);

    kOut<<<dim3(H, 4), 256, smOut>>>(x, Tbuf, rowsBuf, colsBuf, out);
}